// round 13
// baseline (speedup 1.0000x reference)
#include <cuda_runtime.h>
#include <cuda_bf16.h>
#include <cuda_fp16.h>
#include <cstdint>

#define BDIM 32
#define TDIM 512
#define HID  1024
#define NH   16
#define HD   64
#define BT   (BDIM * TDIM)   // 16384

// ------------------------- scratch (device globals) -------------------------
__device__ float  g_scr[(size_t)4 * BDIM * HID];   // o-proj partial maxes
__device__ __half g_xh [(size_t)BT * HID];
__device__ __half g_qh [(size_t)BT * HID];         // pre-scaled by 0.125*log2(e)
__device__ __half g_kh [(size_t)BT * HID];
__device__ __half g_vh [(size_t)BT * HID];
__device__ __half g_ch [(size_t)BT * HID];
__device__ __half g_whf[(size_t)4 * HID * HID];    // fp16 weights (q,k,v,o)

// ------------------------------ PTX helpers --------------------------------
__device__ __forceinline__ uint32_t smem_u32(const void* p) {
    uint32_t a;
    asm("{ .reg .u64 t; cvta.to.shared.u64 t, %1; cvt.u32.u64 %0, t; }" : "=r"(a) : "l"(p));
    return a;
}
__device__ __forceinline__ void ldm_x4(uint32_t* r, uint32_t addr) {
    asm volatile("ldmatrix.sync.aligned.m8n8.x4.shared.b16 {%0,%1,%2,%3}, [%4];"
                 : "=r"(r[0]), "=r"(r[1]), "=r"(r[2]), "=r"(r[3]) : "r"(addr));
}
__device__ __forceinline__ void ldm_x4_t(uint32_t* r, uint32_t addr) {
    asm volatile("ldmatrix.sync.aligned.m8n8.x4.trans.shared.b16 {%0,%1,%2,%3}, [%4];"
                 : "=r"(r[0]), "=r"(r[1]), "=r"(r[2]), "=r"(r[3]) : "r"(addr));
}
// fp32-acc fp16 mma (attention PV)
__device__ __forceinline__ void mma_f16(float* c, const uint32_t* a, const uint32_t* b) {
    asm volatile("mma.sync.aligned.m16n8k16.row.col.f32.f16.f16.f32 "
                 "{%0,%1,%2,%3}, {%4,%5,%6,%7}, {%8,%9}, {%0,%1,%2,%3};"
                 : "+f"(c[0]), "+f"(c[1]), "+f"(c[2]), "+f"(c[3])
                 : "r"(a[0]), "r"(a[1]), "r"(a[2]), "r"(a[3]), "r"(b[0]), "r"(b[1]));
}
// fp16-acc fp16 mma: C fragment = 2 packed half2 regs
__device__ __forceinline__ void mma_f16h(uint32_t* c, const uint32_t* a, const uint32_t* b) {
    asm volatile("mma.sync.aligned.m16n8k16.row.col.f16.f16.f16.f16 "
                 "{%0,%1}, {%2,%3,%4,%5}, {%6,%7}, {%0,%1};"
                 : "+r"(c[0]), "+r"(c[1])
                 : "r"(a[0]), "r"(a[1]), "r"(a[2]), "r"(a[3]), "r"(b[0]), "r"(b[1]));
}
#define CP_ASYNC16(saddr, gptr) \
    asm volatile("cp.async.cg.shared.global [%0], [%1], 16;" :: "r"(saddr), "l"(gptr))
#define CP_COMMIT() asm volatile("cp.async.commit_group;" ::: "memory")
#define CP_WAIT0()  asm volatile("cp.async.wait_group 0;" ::: "memory")
#define CP_WAIT1()  asm volatile("cp.async.wait_group 1;" ::: "memory")

__device__ __forceinline__ uint32_t pack_h_hi(float a, float b) {
    __half2 h = __floats2half2_rn(a, b);
    return *(uint32_t*)&h;
}
__device__ __forceinline__ uint32_t h2ex2(uint32_t x) {
    uint32_t r;
    asm("ex2.approx.f16x2 %0, %1;" : "=r"(r) : "r"(x));
    return r;
}

#define LOG2E_8 0.1803368801111244f     // 0.125 * log2(e) (folded into Q)
#define CLIP2F  72.134752044448170f     // 50 * log2(e)

// ---------------------------------------------------------------------------
// fp16 GEMM core v3: C = A @ W^T, fp16-acc per K=64 chunk, fp32 promote between.
// CTA 128x128, 512 threads, 16 warps (4m x 4n), warp tile 32x32.
// 3-stage cp.async ring, ONE __syncthreads per iteration.
// regs ~90 => 1 CTA/SM = 16 warps = 4 warps/SMSP (same as before).
// ---------------------------------------------------------------------------
#define BK      64
#define NCHUNK  (HID / BK)          // 16
#define PITCH   72                  // fp16 elems per smem row (144B)
#define P2      (PITCH * 2)
#define TILE_B  (128 * P2)          // 18432 bytes
#define STAGE_B (2 * TILE_B)        // 36864
#define GEMM_SMEM_BYTES (3 * STAGE_B)   // 110592
#define GTH     512

struct GemmCore {
    uint32_t sbase;
    int tid, wid, lane, wm, wn, m0, n0;
    float acc[2][4][4];

    __device__ __forceinline__ void init(uint32_t sb, int m, int n) {
        sbase = sb;
        tid = threadIdx.x; wid = tid >> 5; lane = tid & 31;
        wm = wid >> 2; wn = wid & 3;          // 4m x 4n
        m0 = m; n0 = n;
#pragma unroll
        for (int i = 0; i < 2; ++i)
#pragma unroll
            for (int j = 0; j < 4; ++j)
#pragma unroll
                for (int e = 0; e < 4; ++e) acc[i][j][e] = 0.f;
    }

    __device__ __forceinline__ void issue_copy(
        const __half* A, const __half* W, int c, int s)
    {
        const int k0 = c * BK;
        const uint32_t sb = sbase + s * STAGE_B;
#pragma unroll
        for (int op = 0; op < 2; ++op) {
            const __half* src = (op == 0) ? A : W;
            const int rbase = (op == 0) ? m0 : n0;
#pragma unroll
            for (int i = 0; i < 2; ++i) {
                const int u   = i * GTH + tid;     // 1024 uint4 per operand
                const int row = u >> 3;
                const int cv  = u & 7;
                const void* g = src + (size_t)(rbase + row) * HID + k0 + cv * 8;
                CP_ASYNC16(sb + op * TILE_B + row * P2 + cv * 16, g);
            }
        }
        CP_COMMIT();
    }

    __device__ __forceinline__ void compute(int s) {
        const uint32_t sb = sbase + s * STAGE_B;
        const uint32_t aA = sb;
        const uint32_t aW = sb + TILE_B;

        const int arow = wm * 32 + (lane & 15);
        const int acol = (lane >> 4) * 8;
        const int brow = wn * 32 + (lane & 7) + (lane >> 4) * 8;
        const int bcol = ((lane >> 3) & 1) * 8;

        uint32_t hacc[2][4][2];
#pragma unroll
        for (int i = 0; i < 2; ++i)
#pragma unroll
            for (int j = 0; j < 4; ++j) { hacc[i][j][0] = 0; hacc[i][j][1] = 0; }

#pragma unroll
        for (int ks = 0; ks < 4; ++ks) {
            uint32_t a[2][4];
#pragma unroll
            for (int i = 0; i < 2; ++i) {
                const uint32_t off = (arow + i * 16) * P2 + (ks * 16 + acol) * 2;
                ldm_x4(a[i], aA + off);
            }
            uint32_t bw[2][4];
#pragma unroll
            for (int jj = 0; jj < 2; ++jj) {
                const uint32_t off = (brow + jj * 16) * P2 + (ks * 16 + bcol) * 2;
                ldm_x4(bw[jj], aW + off);
            }
#pragma unroll
            for (int i = 0; i < 2; ++i)
#pragma unroll
                for (int j = 0; j < 4; ++j)
                    mma_f16h(hacc[i][j], a[i], &bw[j >> 1][(j & 1) * 2]);
        }
        // promote chunk partials to fp32
#pragma unroll
        for (int i = 0; i < 2; ++i)
#pragma unroll
            for (int j = 0; j < 4; ++j) {
                const float2 f0 = __half22float2(*(const __half2*)&hacc[i][j][0]);
                const float2 f1 = __half22float2(*(const __half2*)&hacc[i][j][1]);
                acc[i][j][0] += f0.x; acc[i][j][1] += f0.y;
                acc[i][j][2] += f1.x; acc[i][j][3] += f1.y;
            }
    }

    __device__ __forceinline__ void mainloop(const __half* A, const __half* W)
    {
        issue_copy(A, W, 0, 0);
        issue_copy(A, W, 1, 1);
#pragma unroll 1
        for (int c = 0; c < NCHUNK; ++c) {
            if (c + 1 < NCHUNK) { CP_WAIT1(); } else { CP_WAIT0(); }
            __syncthreads();
            if (c + 2 < NCHUNK) issue_copy(A, W, c + 2, (c + 2) % 3);
            compute(c % 3);
        }
    }
};

// ---- fused QKV; q output pre-scaled by LOG2E_8 for log2-domain softmax ----
__global__ void __launch_bounds__(GTH)
gemm_qkv_kernel(const __half* __restrict__ xh, const __half* __restrict__ whf,
                const float* __restrict__ bq, const float* __restrict__ bk,
                const float* __restrict__ bv,
                __half* __restrict__ qh, __half* __restrict__ kh,
                __half* __restrict__ vh)
{
    extern __shared__ __align__(128) char smem[];
    const int z = blockIdx.z;
    const size_t WSZ = (size_t)HID * HID;
    const float* bias = (z == 0) ? bq : (z == 1) ? bk : bv;
    __half* C = (z == 0) ? qh : (z == 1) ? kh : vh;
    const float sc = (z == 0) ? LOG2E_8 : 1.f;

    GemmCore g;
    g.init(smem_u32(smem), blockIdx.y * 128, blockIdx.x * 128);
    g.mainloop(xh, whf + z * WSZ);

#pragma unroll
    for (int i = 0; i < 2; ++i) {
        const int r0 = g.m0 + g.wm * 32 + i * 16 + (g.lane >> 2);
#pragma unroll
        for (int j = 0; j < 4; ++j) {
            const int col = g.n0 + g.wn * 32 + j * 8 + (g.lane & 3) * 2;
            const float bx = bias[col], by = bias[col + 1];
            const size_t o0 = (size_t)r0 * HID + col;
            const size_t o1 = (size_t)(r0 + 8) * HID + col;
            *(uint32_t*)(C + o0) = pack_h_hi((g.acc[i][j][0] + bx) * sc,
                                             (g.acc[i][j][1] + by) * sc);
            *(uint32_t*)(C + o1) = pack_h_hi((g.acc[i][j][2] + bx) * sc,
                                             (g.acc[i][j][3] + by) * sc);
        }
    }
}

// ---- o-proj with fused column-max epilogue (bias added in combine) ----
__global__ void __launch_bounds__(GTH)
gemm_omax_kernel(const __half* __restrict__ ch, const __half* __restrict__ Wo,
                 float* __restrict__ scr)
{
    extern __shared__ __align__(128) char smem[];
    GemmCore g;
    g.init(smem_u32(smem), blockIdx.y * 128, blockIdx.x * 128);
    g.mainloop(ch, Wo);
    __syncthreads();

    float* maxbuf = (float*)smem;   // [4][128] indexed by wm
#pragma unroll
    for (int j = 0; j < 4; ++j) {
        float c0 = -3.402823466e38f, c1 = c0;
#pragma unroll
        for (int i = 0; i < 2; ++i) {
            c0 = fmaxf(c0, fmaxf(g.acc[i][j][0], g.acc[i][j][2]));
            c1 = fmaxf(c1, fmaxf(g.acc[i][j][1], g.acc[i][j][3]));
        }
        c0 = fmaxf(c0, __shfl_xor_sync(0xffffffff, c0, 4));
        c0 = fmaxf(c0, __shfl_xor_sync(0xffffffff, c0, 8));
        c0 = fmaxf(c0, __shfl_xor_sync(0xffffffff, c0, 16));
        c1 = fmaxf(c1, __shfl_xor_sync(0xffffffff, c1, 4));
        c1 = fmaxf(c1, __shfl_xor_sync(0xffffffff, c1, 8));
        c1 = fmaxf(c1, __shfl_xor_sync(0xffffffff, c1, 16));
        if ((g.lane >> 2) == 0) {
            const int cc = g.wn * 32 + j * 8 + (g.lane & 3) * 2;
            maxbuf[g.wm * 128 + cc]     = c0;
            maxbuf[g.wm * 128 + cc + 1] = c1;
        }
    }
    __syncthreads();
    if (g.tid < 128) {
        const float f = fmaxf(fmaxf(maxbuf[g.tid], maxbuf[128 + g.tid]),
                              fmaxf(maxbuf[256 + g.tid], maxbuf[384 + g.tid]));
        const int b   = g.m0 >> 9;
        const int sub = (g.m0 >> 7) & 3;
        scr[((size_t)sub * BDIM + b) * HID + g.n0 + g.tid] = f;
    }
}

__global__ void __launch_bounds__(256)
maxcombine_kernel(const float* __restrict__ scr, const float* __restrict__ bias,
                  float* __restrict__ out)
{
    const int i = blockIdx.x * 256 + threadIdx.x;
    const float f = fmaxf(fmaxf(scr[i], scr[BDIM * HID + i]),
                          fmaxf(scr[2 * BDIM * HID + i], scr[3 * BDIM * HID + i]));
    out[i] = f + bias[i & (HID - 1)];
}

// ---------------------------------------------------------------------------
// Attention (unchanged from R12): QK fp16-acc, half2 softmax, ex2.f16x2,
// PV fp32-acc, 3-stage KV ring, one sync per chunk.
// ---------------------------------------------------------------------------
#define APITCH 72
#define AP2    (APITCH * 2)
#define SM_Q   0
#define KVST   (64 * AP2)               // 9216
#define SM_K0  (128 * AP2)              // 18432
#define SM_V0  (SM_K0 + 3 * KVST)       // 46080
#define SM_MSK (SM_V0 + 3 * KVST)       // 73728
#define MSKST  256
#define ATTN_SMEM_BYTES (SM_MSK + 3 * MSKST)

__global__ void __launch_bounds__(256)
attn_mma_kernel(const __half* __restrict__ Qh, const __half* __restrict__ Kh,
                const __half* __restrict__ Vh, const int* __restrict__ mask,
                __half* __restrict__ Ch)
{
    extern __shared__ __align__(128) char smem[];
    const uint32_t sb = smem_u32(smem);

    const int tid  = threadIdx.x;
    const int wid  = tid >> 5, lane = tid & 31;
    const int q0   = blockIdx.x * 128;
    const int h    = blockIdx.y;
    const int b    = blockIdx.z;
    const size_t rowbase = (size_t)b * TDIM;
    const int colbase = h * HD;

    const __half2 C2  = __float2half2_rn(CLIP2F);
    const __half2 nC2 = __float2half2_rn(-CLIP2F);

    {
#pragma unroll
        for (int i = 0; i < 4; ++i) {
            const int u = i * 256 + tid;
            const int r = u >> 3, cv = u & 7;
            const void* g = Qh + (rowbase + q0 + r) * HID + colbase + cv * 8;
            CP_ASYNC16(sb + SM_Q + r * AP2 + cv * 16, g);
        }
        CP_COMMIT();
    }

    auto issue_kv = [&](int c, int s) {
        const int k0 = c * 64;
        const uint32_t soK = sb + SM_K0 + s * KVST;
        const uint32_t soV = sb + SM_V0 + s * KVST;
#pragma unroll
        for (int i = 0; i < 2; ++i) {
            const int u = i * 256 + tid;
            const int r = u >> 3, cv = u & 7;
            CP_ASYNC16(soK + r * AP2 + cv * 16,
                       Kh + (rowbase + k0 + r) * HID + colbase + cv * 8);
            CP_ASYNC16(soV + r * AP2 + cv * 16,
                       Vh + (rowbase + k0 + r) * HID + colbase + cv * 8);
        }
        CP_COMMIT();
        if (tid < 32) {
            const int i0 = mask[b * TDIM + k0 + 2 * tid];
            const int i1 = mask[b * TDIM + k0 + 2 * tid + 1];
            const __half2 m2 = __floats2half2_rn((float)i0, (float)i1);
            const __half2 a2 = __hfma2(m2, C2, nC2);
            __half2* mp = (__half2*)(smem + SM_MSK + s * MSKST);
            mp[tid]      = m2;
            mp[32 + tid] = a2;
        }
    };

    float oacc[8][4];
#pragma unroll
    for (int j = 0; j < 8; ++j)
#pragma unroll
        for (int e = 0; e < 4; ++e) oacc[j][e] = 0.f;
    float den_r = 0.f, den_r8 = 0.f;

    const int qoff_row = (wid * 16 + (lane & 15)) * AP2;
    const int qoff_col = ((lane >> 4) * 8) * 2;
    const int koff_row = ((lane & 7) + (lane >> 4) * 8) * AP2;
    const int koff_col = (((lane >> 3) & 1) * 8) * 2;
    const int voff_row = ((lane & 15)) * AP2;
    const int voff_col = ((lane >> 4) * 8) * 2;
    const uint32_t qbase = sb + SM_Q + qoff_row + qoff_col;

    issue_kv(0, 0);
    issue_kv(1, 1);

#pragma unroll 1
    for (int c = 0; c < 8; ++c) {
        const int s = c % 3;
        if (c < 7) { CP_WAIT1(); } else { CP_WAIT0(); }
        __syncthreads();
        if (c + 2 < 8) issue_kv(c + 2, (c + 2) % 3);

        uint32_t sacc[8][2];
#pragma unroll
        for (int j = 0; j < 8; ++j) { sacc[j][0] = 0; sacc[j][1] = 0; }

#pragma unroll
        for (int dk = 0; dk < 4; ++dk) {
            uint32_t a[4];
            ldm_x4(a, qbase + dk * 32);
#pragma unroll
            for (int kb = 0; kb < 4; ++kb) {
                uint32_t bh[4];
                const uint32_t ka = sb + SM_K0 + s * KVST +
                                    (kb * 16) * AP2 + koff_row + dk * 32 + koff_col;
                ldm_x4(bh, ka);
                mma_f16h(sacc[2 * kb],     a, &bh[0]);
                mma_f16h(sacc[2 * kb + 1], a, &bh[2]);
            }
        }

        const __half2* mp = (const __half2*)(smem + SM_MSK + s * MSKST);
        float dr = 0.f, dr8 = 0.f;
#pragma unroll
        for (int nt = 0; nt < 8; ++nt) {
            const int cp = nt * 4 + (lane & 3);
            const __half2 m2 = mp[cp];
            const __half2 a2 = mp[32 + cp];
#pragma unroll
            for (int r = 0; r < 2; ++r) {
                __half2 t2 = *(__half2*)&sacc[nt][r];
                t2 = __hmax2(__hmin2(t2, C2), nC2);
                t2 = __hfma2(m2, t2, a2);
                const uint32_t p = h2ex2(*(uint32_t*)&t2);
                sacc[nt][r] = p;
                const float2 f = __half22float2(*(const __half2*)&p);
                if (r == 0) dr += f.x + f.y; else dr8 += f.x + f.y;
            }
        }
        dr  += __shfl_xor_sync(0xffffffff, dr, 1);
        dr  += __shfl_xor_sync(0xffffffff, dr, 2);
        dr8 += __shfl_xor_sync(0xffffffff, dr8, 1);
        dr8 += __shfl_xor_sync(0xffffffff, dr8, 2);
        den_r  += dr;
        den_r8 += dr8;

#pragma unroll
        for (int kb = 0; kb < 4; ++kb) {
            uint32_t pa[4];
            const int t0 = 2 * kb, t1 = 2 * kb + 1;
            pa[0] = sacc[t0][0];
            pa[1] = sacc[t0][1];
            pa[2] = sacc[t1][0];
            pa[3] = sacc[t1][1];
#pragma unroll
            for (int dnp = 0; dnp < 4; ++dnp) {
                uint32_t vv[4];
                const uint32_t va = sb + SM_V0 + s * KVST +
                                    (kb * 16) * AP2 + voff_row + dnp * 32 + voff_col;
                ldm_x4_t(vv, va);
                mma_f16(oacc[2 * dnp],     pa, &vv[0]);
                mma_f16(oacc[2 * dnp + 1], pa, &vv[2]);
            }
        }
    }

    const float invr  = 1.f / den_r;
    const float invr8 = 1.f / den_r8;
    const size_t r0 = (rowbase + q0 + wid * 16 + (lane >> 2)) * HID + colbase;
    const size_t r8 = r0 + 8 * HID;
#pragma unroll
    for (int dn = 0; dn < 8; ++dn) {
        const int col = dn * 8 + (lane & 3) * 2;
        *(uint32_t*)(Ch + r0 + col) = pack_h_hi(oacc[dn][0] * invr,  oacc[dn][1] * invr);
        *(uint32_t*)(Ch + r8 + col) = pack_h_hi(oacc[dn][2] * invr8, oacc[dn][3] * invr8);
    }
}

// ---------------------------------------------------------------------------
// Merged prep: z<32 -> x transpose+fp16 (64x64 tiles); z>=32 -> weight fp32->fp16.
// ---------------------------------------------------------------------------
__global__ void __launch_bounds__(256)
prep_kernel(const float* __restrict__ x, __half* __restrict__ xh,
            const float* __restrict__ w0, const float* __restrict__ w1,
            const float* __restrict__ w2, const float* __restrict__ w3,
            __half* __restrict__ whf)
{
    const int z = blockIdx.z;
    const int tid = threadIdx.x;

    if (z >= 32) {
        // weight convert: 4096 virtual blocks of 256 float4
        const int bid = (z - 32) * 128 + blockIdx.y * 8 + blockIdx.x;
        const int w = bid >> 10;                 // 0..3
        const int i = (bid & 1023) * 256 + tid;  // uint4 index within weight
        const float* src = (w == 0) ? w0 : (w == 1) ? w1 : (w == 2) ? w2 : w3;
        __half* d = whf + (size_t)w * HID * HID;
        const float4 v = ((const float4*)src)[i];
        uint2 hp;
        hp.x = pack_h_hi(v.x, v.y);
        hp.y = pack_h_hi(v.z, v.w);
        ((uint2*)d)[i] = hp;
        return;
    }

    __shared__ float s[64][65];
    const int b = z, k0 = blockIdx.y * 64, t0 = blockIdx.x * 64;
    const float* src = x + ((size_t)b * HID + k0) * TDIM + t0;
#pragma unroll
    for (int i = 0; i < 4; ++i) {
        const int u  = i * 256 + tid;
        const int r  = u >> 4;
        const int c4 = u & 15;
        const float4 v = *(const float4*)(src + (size_t)r * TDIM + c4 * 4);
        s[r][c4 * 4 + 0] = v.x;
        s[r][c4 * 4 + 1] = v.y;
        s[r][c4 * 4 + 2] = v.z;
        s[r][c4 * 4 + 3] = v.w;
    }
    __syncthreads();

    const int t  = tid >> 2;
    const int kc = (tid & 3) * 16;
    uint32_t o[8];
#pragma unroll
    for (int i = 0; i < 8; ++i)
        o[i] = pack_h_hi(s[kc + 2 * i][t], s[kc + 2 * i + 1][t]);
    __half* dst = xh + (size_t)(b * TDIM + t0 + t) * HID + k0 + kc;
    *(uint4*)(dst)     = make_uint4(o[0], o[1], o[2], o[3]);
    *(uint4*)(dst + 8) = make_uint4(o[4], o[5], o[6], o[7]);
}

// ---------------------------------------------------------------------------
extern "C" void kernel_launch(void* const* d_in, const int* in_sizes, int n_in,
                              void* d_out, int out_size)
{
    const float* x    = (const float*)d_in[0];
    const int*   mask = (const int*)d_in[1];
    const float* Wq   = (const float*)d_in[2];
    const float* bq   = (const float*)d_in[3];
    const float* Wk   = (const float*)d_in[4];
    const float* bk   = (const float*)d_in[5];
    const float* Wv   = (const float*)d_in[6];
    const float* bv   = (const float*)d_in[7];
    const float* Wo   = (const float*)d_in[8];
    const float* bo   = (const float*)d_in[9];
    float* out = (float*)d_out;

    float* scr;
    __half *xh, *qh, *kh, *vh, *ch, *whf;
    cudaGetSymbolAddress((void**)&scr, g_scr);
    cudaGetSymbolAddress((void**)&xh,  g_xh);
    cudaGetSymbolAddress((void**)&qh,  g_qh);
    cudaGetSymbolAddress((void**)&kh,  g_kh);
    cudaGetSymbolAddress((void**)&vh,  g_vh);
    cudaGetSymbolAddress((void**)&ch,  g_ch);
    cudaGetSymbolAddress((void**)&whf, g_whf);

    cudaFuncSetAttribute(gemm_qkv_kernel,
                         cudaFuncAttributeMaxDynamicSharedMemorySize, GEMM_SMEM_BYTES);
    cudaFuncSetAttribute(gemm_omax_kernel,
                         cudaFuncAttributeMaxDynamicSharedMemorySize, GEMM_SMEM_BYTES);
    cudaFuncSetAttribute(attn_mma_kernel,
                         cudaFuncAttributeMaxDynamicSharedMemorySize, ATTN_SMEM_BYTES);

    // prep: grid (8,16,64): z<32 xpose (8*16 tiles per batch), z>=32 wconv (4096 blocks)
    prep_kernel<<<dim3(8, 16, 64), 256>>>(x, xh, Wq, Wk, Wv, Wo, whf);

    const size_t WSZ = (size_t)HID * HID;

    gemm_qkv_kernel<<<dim3(HID / 128, BT / 128, 3), GTH, GEMM_SMEM_BYTES>>>(
        xh, whf, bq, bk, bv, qh, kh, vh);

    attn_mma_kernel<<<dim3(TDIM / 128, NH, BDIM), 256, ATTN_SMEM_BYTES>>>(
        qh, kh, vh, mask, ch);

    gemm_omax_kernel<<<dim3(HID / 128, BT / 128), GTH, GEMM_SMEM_BYTES>>>(
        ch, whf + 3 * WSZ, scr);

    maxcombine_kernel<<<(BDIM * HID) / 256, 256>>>(scr, bo, out);
}

// round 14
// speedup vs baseline: 1.2988x; 1.2988x over previous
#include <cuda_runtime.h>
#include <cuda_bf16.h>
#include <cuda_fp16.h>
#include <cstdint>

#define BDIM 32
#define TDIM 512
#define HID  1024
#define NH   16
#define HD   64
#define BT   (BDIM * TDIM)   // 16384

// ------------------------- scratch (device globals) -------------------------
__device__ float  g_scr[(size_t)4 * BDIM * HID];   // o-proj partial maxes
__device__ __half g_xh [(size_t)BT * HID];
__device__ __half g_qh [(size_t)BT * HID];         // pre-scaled by 0.125*log2(e)
__device__ __half g_kh [(size_t)BT * HID];
__device__ __half g_vh [(size_t)BT * HID];
__device__ __half g_ch [(size_t)BT * HID];
__device__ __half g_whf[(size_t)4 * HID * HID];    // fp16 weights (q,k,v,o)

// ------------------------------ PTX helpers --------------------------------
__device__ __forceinline__ uint32_t smem_u32(const void* p) {
    uint32_t a;
    asm("{ .reg .u64 t; cvta.to.shared.u64 t, %1; cvt.u32.u64 %0, t; }" : "=r"(a) : "l"(p));
    return a;
}
__device__ __forceinline__ void ldm_x4(uint32_t* r, uint32_t addr) {
    asm volatile("ldmatrix.sync.aligned.m8n8.x4.shared.b16 {%0,%1,%2,%3}, [%4];"
                 : "=r"(r[0]), "=r"(r[1]), "=r"(r[2]), "=r"(r[3]) : "r"(addr));
}
__device__ __forceinline__ void ldm_x4_t(uint32_t* r, uint32_t addr) {
    asm volatile("ldmatrix.sync.aligned.m8n8.x4.trans.shared.b16 {%0,%1,%2,%3}, [%4];"
                 : "=r"(r[0]), "=r"(r[1]), "=r"(r[2]), "=r"(r[3]) : "r"(addr));
}
// fp32-acc fp16 mma (projections, PV)
__device__ __forceinline__ void mma_f16(float* c, const uint32_t* a, const uint32_t* b) {
    asm volatile("mma.sync.aligned.m16n8k16.row.col.f32.f16.f16.f32 "
                 "{%0,%1,%2,%3}, {%4,%5,%6,%7}, {%8,%9}, {%0,%1,%2,%3};"
                 : "+f"(c[0]), "+f"(c[1]), "+f"(c[2]), "+f"(c[3])
                 : "r"(a[0]), "r"(a[1]), "r"(a[2]), "r"(a[3]), "r"(b[0]), "r"(b[1]));
}
// fp16-acc fp16 mma (attention QK): C fragment = 2 packed half2 regs
__device__ __forceinline__ void mma_f16h(uint32_t* c, const uint32_t* a, const uint32_t* b) {
    asm volatile("mma.sync.aligned.m16n8k16.row.col.f16.f16.f16.f16 "
                 "{%0,%1}, {%2,%3,%4,%5}, {%6,%7}, {%0,%1};"
                 : "+r"(c[0]), "+r"(c[1])
                 : "r"(a[0]), "r"(a[1]), "r"(a[2]), "r"(a[3]), "r"(b[0]), "r"(b[1]));
}
#define CP_ASYNC16(saddr, gptr) \
    asm volatile("cp.async.cg.shared.global [%0], [%1], 16;" :: "r"(saddr), "l"(gptr))
#define CP_COMMIT() asm volatile("cp.async.commit_group;" ::: "memory")
#define CP_WAIT0()  asm volatile("cp.async.wait_group 0;" ::: "memory")
#define CP_WAIT1()  asm volatile("cp.async.wait_group 1;" ::: "memory")

__device__ __forceinline__ uint32_t pack_h_hi(float a, float b) {
    __half2 h = __floats2half2_rn(a, b);
    return *(uint32_t*)&h;
}
__device__ __forceinline__ uint32_t h2ex2(uint32_t x) {
    uint32_t r;
    asm("ex2.approx.f16x2 %0, %1;" : "=r"(r) : "r"(x));
    return r;
}

#define LOG2E_8 0.1803368801111244f     // 0.125 * log2(e) (folded into Q)
#define CLIP2F  72.134752044448170f     // 50 * log2(e)

// ---------------------------------------------------------------------------
// fp16 GEMM core (R12 proven config): C = A @ W^T (fp32 acc)
// 128x128 tile, BK=64, 8 warps (2m x 4n), warp tile 64x32.
// 3-stage cp.async ring, ONE __syncthreads per iteration.
// ---------------------------------------------------------------------------
#define BK      64
#define NCHUNK  (HID / BK)          // 16
#define PITCH   72                  // fp16 elems per smem row (144B)
#define P2      (PITCH * 2)
#define TILE_B  (128 * P2)          // 18432 bytes
#define STAGE_B (2 * TILE_B)        // 36864
#define GEMM_SMEM_BYTES (3 * STAGE_B)   // 110592

struct GemmCore {
    uint32_t sbase;
    int tid, wid, lane, wm, wn, m0, n0;
    float acc[4][4][4];

    __device__ __forceinline__ void init(uint32_t sb, int m, int n) {
        sbase = sb;
        tid = threadIdx.x; wid = tid >> 5; lane = tid & 31;
        wm = wid >> 2; wn = wid & 3;
        m0 = m; n0 = n;
#pragma unroll
        for (int i = 0; i < 4; ++i)
#pragma unroll
            for (int j = 0; j < 4; ++j)
#pragma unroll
                for (int e = 0; e < 4; ++e) acc[i][j][e] = 0.f;
    }

    __device__ __forceinline__ void issue_copy(
        const __half* A, const __half* W, int c, int s)
    {
        const int k0 = c * BK;
        const uint32_t sb = sbase + s * STAGE_B;
#pragma unroll
        for (int op = 0; op < 2; ++op) {
            const __half* src = (op == 0) ? A : W;
            const int rbase = (op == 0) ? m0 : n0;
#pragma unroll
            for (int i = 0; i < 4; ++i) {
                const int u   = i * 256 + tid;
                const int row = u >> 3;
                const int cv  = u & 7;
                const void* g = src + (size_t)(rbase + row) * HID + k0 + cv * 8;
                CP_ASYNC16(sb + op * TILE_B + row * P2 + cv * 16, g);
            }
        }
        CP_COMMIT();
    }

    __device__ __forceinline__ void compute(int s) {
        const uint32_t sb = sbase + s * STAGE_B;
        const uint32_t aA = sb;
        const uint32_t aW = sb + TILE_B;

        const int arow = wm * 64 + (lane & 15);
        const int acol = (lane >> 4) * 8;
        const int brow = wn * 32 + (lane & 7) + (lane >> 4) * 8;
        const int bcol = ((lane >> 3) & 1) * 8;

#pragma unroll
        for (int ks = 0; ks < 4; ++ks) {
            uint32_t a[4][4];
#pragma unroll
            for (int i = 0; i < 4; ++i) {
                const uint32_t off = (arow + i * 16) * P2 + (ks * 16 + acol) * 2;
                ldm_x4(a[i], aA + off);
            }
            uint32_t bw[8];
#pragma unroll
            for (int jj = 0; jj < 2; ++jj) {
                const uint32_t off = (brow + jj * 16) * P2 + (ks * 16 + bcol) * 2;
                ldm_x4(&bw[jj * 4], aW + off);
            }
#pragma unroll
            for (int i = 0; i < 4; ++i)
#pragma unroll
                for (int j = 0; j < 4; ++j) {
                    const int bi = (j >> 1) * 4 + (j & 1) * 2;
                    mma_f16(acc[i][j], a[i], &bw[bi]);
                }
        }
    }

    __device__ __forceinline__ void mainloop(const __half* A, const __half* W)
    {
        issue_copy(A, W, 0, 0);
        issue_copy(A, W, 1, 1);
#pragma unroll 1
        for (int c = 0; c < NCHUNK; ++c) {
            if (c + 1 < NCHUNK) { CP_WAIT1(); } else { CP_WAIT0(); }
            __syncthreads();
            if (c + 2 < NCHUNK) issue_copy(A, W, c + 2, (c + 2) % 3);
            compute(c % 3);
        }
    }
};

// ---- fused QKV; q output pre-scaled by LOG2E_8 for log2-domain softmax ----
__global__ void __launch_bounds__(256)
gemm_qkv_kernel(const __half* __restrict__ xh, const __half* __restrict__ whf,
                const float* __restrict__ bq, const float* __restrict__ bk,
                const float* __restrict__ bv,
                __half* __restrict__ qh, __half* __restrict__ kh,
                __half* __restrict__ vh)
{
    extern __shared__ __align__(128) char smem[];
    const int z = blockIdx.z;
    const size_t WSZ = (size_t)HID * HID;
    const float* bias = (z == 0) ? bq : (z == 1) ? bk : bv;
    __half* C = (z == 0) ? qh : (z == 1) ? kh : vh;
    const float sc = (z == 0) ? LOG2E_8 : 1.f;

    GemmCore g;
    g.init(smem_u32(smem), blockIdx.y * 128, blockIdx.x * 128);
    g.mainloop(xh, whf + z * WSZ);

#pragma unroll
    for (int i = 0; i < 4; ++i) {
        const int r0 = g.m0 + g.wm * 64 + i * 16 + (g.lane >> 2);
#pragma unroll
        for (int j = 0; j < 4; ++j) {
            const int col = g.n0 + g.wn * 32 + j * 8 + (g.lane & 3) * 2;
            const float bx = bias[col], by = bias[col + 1];
            const size_t o0 = (size_t)r0 * HID + col;
            const size_t o1 = (size_t)(r0 + 8) * HID + col;
            *(uint32_t*)(C + o0) = pack_h_hi((g.acc[i][j][0] + bx) * sc,
                                             (g.acc[i][j][1] + by) * sc);
            *(uint32_t*)(C + o1) = pack_h_hi((g.acc[i][j][2] + bx) * sc,
                                             (g.acc[i][j][3] + by) * sc);
        }
    }
}

// ---- o-proj with fused column-max epilogue (bias added in combine) ----
__global__ void __launch_bounds__(256)
gemm_omax_kernel(const __half* __restrict__ ch, const __half* __restrict__ Wo,
                 float* __restrict__ scr)
{
    extern __shared__ __align__(128) char smem[];
    GemmCore g;
    g.init(smem_u32(smem), blockIdx.y * 128, blockIdx.x * 128);
    g.mainloop(ch, Wo);
    __syncthreads();

    float* maxbuf = (float*)smem;   // [2][128] indexed by wm
#pragma unroll
    for (int j = 0; j < 4; ++j) {
        float c0 = -3.402823466e38f, c1 = c0;
#pragma unroll
        for (int i = 0; i < 4; ++i) {
            c0 = fmaxf(c0, fmaxf(g.acc[i][j][0], g.acc[i][j][2]));
            c1 = fmaxf(c1, fmaxf(g.acc[i][j][1], g.acc[i][j][3]));
        }
        c0 = fmaxf(c0, __shfl_xor_sync(0xffffffff, c0, 4));
        c0 = fmaxf(c0, __shfl_xor_sync(0xffffffff, c0, 8));
        c0 = fmaxf(c0, __shfl_xor_sync(0xffffffff, c0, 16));
        c1 = fmaxf(c1, __shfl_xor_sync(0xffffffff, c1, 4));
        c1 = fmaxf(c1, __shfl_xor_sync(0xffffffff, c1, 8));
        c1 = fmaxf(c1, __shfl_xor_sync(0xffffffff, c1, 16));
        if ((g.lane >> 2) == 0) {
            const int cc = g.wn * 32 + j * 8 + (g.lane & 3) * 2;
            maxbuf[g.wm * 128 + cc]     = c0;
            maxbuf[g.wm * 128 + cc + 1] = c1;
        }
    }
    __syncthreads();
    if (g.tid < 128) {
        const float f = fmaxf(maxbuf[g.tid], maxbuf[128 + g.tid]);
        const int b   = g.m0 >> 9;
        const int sub = (g.m0 >> 7) & 3;
        scr[((size_t)sub * BDIM + b) * HID + g.n0 + g.tid] = f;
    }
}

__global__ void __launch_bounds__(256)
maxcombine_kernel(const float* __restrict__ scr, const float* __restrict__ bias,
                  float* __restrict__ out)
{
    const int i = blockIdx.x * 256 + threadIdx.x;
    const float f = fmaxf(fmaxf(scr[i], scr[BDIM * HID + i]),
                          fmaxf(scr[2 * BDIM * HID + i], scr[3 * BDIM * HID + i]));
    out[i] = f + bias[i & (HID - 1)];
}

// ---------------------------------------------------------------------------
// Attention (R12 proven): QK fp16-acc (packed half2 C-frags), half2 softmax,
// ex2.f16x2, PV fp32-acc, 3-stage KV ring, one sync per chunk.
// ---------------------------------------------------------------------------
#define APITCH 72
#define AP2    (APITCH * 2)
#define SM_Q   0
#define KVST   (64 * AP2)               // 9216
#define SM_K0  (128 * AP2)              // 18432
#define SM_V0  (SM_K0 + 3 * KVST)       // 46080
#define SM_MSK (SM_V0 + 3 * KVST)       // 73728
#define MSKST  256
#define ATTN_SMEM_BYTES (SM_MSK + 3 * MSKST)

__global__ void __launch_bounds__(256)
attn_mma_kernel(const __half* __restrict__ Qh, const __half* __restrict__ Kh,
                const __half* __restrict__ Vh, const int* __restrict__ mask,
                __half* __restrict__ Ch)
{
    extern __shared__ __align__(128) char smem[];
    const uint32_t sb = smem_u32(smem);

    const int tid  = threadIdx.x;
    const int wid  = tid >> 5, lane = tid & 31;
    const int q0   = blockIdx.x * 128;
    const int h    = blockIdx.y;
    const int b    = blockIdx.z;
    const size_t rowbase = (size_t)b * TDIM;
    const int colbase = h * HD;

    const __half2 C2  = __float2half2_rn(CLIP2F);
    const __half2 nC2 = __float2half2_rn(-CLIP2F);

    {
#pragma unroll
        for (int i = 0; i < 4; ++i) {
            const int u = i * 256 + tid;
            const int r = u >> 3, cv = u & 7;
            const void* g = Qh + (rowbase + q0 + r) * HID + colbase + cv * 8;
            CP_ASYNC16(sb + SM_Q + r * AP2 + cv * 16, g);
        }
        CP_COMMIT();
    }

    auto issue_kv = [&](int c, int s) {
        const int k0 = c * 64;
        const uint32_t soK = sb + SM_K0 + s * KVST;
        const uint32_t soV = sb + SM_V0 + s * KVST;
#pragma unroll
        for (int i = 0; i < 2; ++i) {
            const int u = i * 256 + tid;
            const int r = u >> 3, cv = u & 7;
            CP_ASYNC16(soK + r * AP2 + cv * 16,
                       Kh + (rowbase + k0 + r) * HID + colbase + cv * 8);
            CP_ASYNC16(soV + r * AP2 + cv * 16,
                       Vh + (rowbase + k0 + r) * HID + colbase + cv * 8);
        }
        CP_COMMIT();
        if (tid < 32) {
            const int i0 = mask[b * TDIM + k0 + 2 * tid];
            const int i1 = mask[b * TDIM + k0 + 2 * tid + 1];
            const __half2 m2 = __floats2half2_rn((float)i0, (float)i1);
            const __half2 a2 = __hfma2(m2, C2, nC2);
            __half2* mp = (__half2*)(smem + SM_MSK + s * MSKST);
            mp[tid]      = m2;
            mp[32 + tid] = a2;
        }
    };

    float oacc[8][4];
#pragma unroll
    for (int j = 0; j < 8; ++j)
#pragma unroll
        for (int e = 0; e < 4; ++e) oacc[j][e] = 0.f;
    float den_r = 0.f, den_r8 = 0.f;

    const int qoff_row = (wid * 16 + (lane & 15)) * AP2;
    const int qoff_col = ((lane >> 4) * 8) * 2;
    const int koff_row = ((lane & 7) + (lane >> 4) * 8) * AP2;
    const int koff_col = (((lane >> 3) & 1) * 8) * 2;
    const int voff_row = ((lane & 15)) * AP2;
    const int voff_col = ((lane >> 4) * 8) * 2;
    const uint32_t qbase = sb + SM_Q + qoff_row + qoff_col;

    issue_kv(0, 0);
    issue_kv(1, 1);

#pragma unroll 1
    for (int c = 0; c < 8; ++c) {
        const int s = c % 3;
        if (c < 7) { CP_WAIT1(); } else { CP_WAIT0(); }
        __syncthreads();
        if (c + 2 < 8) issue_kv(c + 2, (c + 2) % 3);

        uint32_t sacc[8][2];
#pragma unroll
        for (int j = 0; j < 8; ++j) { sacc[j][0] = 0; sacc[j][1] = 0; }

#pragma unroll
        for (int dk = 0; dk < 4; ++dk) {
            uint32_t a[4];
            ldm_x4(a, qbase + dk * 32);
#pragma unroll
            for (int kb = 0; kb < 4; ++kb) {
                uint32_t bh[4];
                const uint32_t ka = sb + SM_K0 + s * KVST +
                                    (kb * 16) * AP2 + koff_row + dk * 32 + koff_col;
                ldm_x4(bh, ka);
                mma_f16h(sacc[2 * kb],     a, &bh[0]);
                mma_f16h(sacc[2 * kb + 1], a, &bh[2]);
            }
        }

        const __half2* mp = (const __half2*)(smem + SM_MSK + s * MSKST);
        float dr = 0.f, dr8 = 0.f;
#pragma unroll
        for (int nt = 0; nt < 8; ++nt) {
            const int cp = nt * 4 + (lane & 3);
            const __half2 m2 = mp[cp];
            const __half2 a2 = mp[32 + cp];
#pragma unroll
            for (int r = 0; r < 2; ++r) {
                __half2 t2 = *(__half2*)&sacc[nt][r];
                t2 = __hmax2(__hmin2(t2, C2), nC2);
                t2 = __hfma2(m2, t2, a2);
                const uint32_t p = h2ex2(*(uint32_t*)&t2);
                sacc[nt][r] = p;
                const float2 f = __half22float2(*(const __half2*)&p);
                if (r == 0) dr += f.x + f.y; else dr8 += f.x + f.y;
            }
        }
        dr  += __shfl_xor_sync(0xffffffff, dr, 1);
        dr  += __shfl_xor_sync(0xffffffff, dr, 2);
        dr8 += __shfl_xor_sync(0xffffffff, dr8, 1);
        dr8 += __shfl_xor_sync(0xffffffff, dr8, 2);
        den_r  += dr;
        den_r8 += dr8;

#pragma unroll
        for (int kb = 0; kb < 4; ++kb) {
            uint32_t pa[4];
            const int t0 = 2 * kb, t1 = 2 * kb + 1;
            pa[0] = sacc[t0][0];
            pa[1] = sacc[t0][1];
            pa[2] = sacc[t1][0];
            pa[3] = sacc[t1][1];
#pragma unroll
            for (int dnp = 0; dnp < 4; ++dnp) {
                uint32_t vv[4];
                const uint32_t va = sb + SM_V0 + s * KVST +
                                    (kb * 16) * AP2 + voff_row + dnp * 32 + voff_col;
                ldm_x4_t(vv, va);
                mma_f16(oacc[2 * dnp],     pa, &vv[0]);
                mma_f16(oacc[2 * dnp + 1], pa, &vv[2]);
            }
        }
    }

    const float invr  = 1.f / den_r;
    const float invr8 = 1.f / den_r8;
    const size_t r0 = (rowbase + q0 + wid * 16 + (lane >> 2)) * HID + colbase;
    const size_t r8 = r0 + 8 * HID;
#pragma unroll
    for (int dn = 0; dn < 8; ++dn) {
        const int col = dn * 8 + (lane & 3) * 2;
        *(uint32_t*)(Ch + r0 + col) = pack_h_hi(oacc[dn][0] * invr,  oacc[dn][1] * invr);
        *(uint32_t*)(Ch + r8 + col) = pack_h_hi(oacc[dn][2] * invr8, oacc[dn][3] * invr8);
    }
}

// ---------------------------------------------------------------------------
// Merged prep: z<32 -> x transpose+fp16 (64x64 tiles); z>=32 -> weight fp32->fp16.
// ---------------------------------------------------------------------------
__global__ void __launch_bounds__(256)
prep_kernel(const float* __restrict__ x, __half* __restrict__ xh,
            const float* __restrict__ w0, const float* __restrict__ w1,
            const float* __restrict__ w2, const float* __restrict__ w3,
            __half* __restrict__ whf)
{
    const int z = blockIdx.z;
    const int tid = threadIdx.x;

    if (z >= 32) {
        const int bid = (z - 32) * 128 + blockIdx.y * 8 + blockIdx.x;
        const int w = bid >> 10;
        const int i = (bid & 1023) * 256 + tid;
        const float* src = (w == 0) ? w0 : (w == 1) ? w1 : (w == 2) ? w2 : w3;
        __half* d = whf + (size_t)w * HID * HID;
        const float4 v = ((const float4*)src)[i];
        uint2 hp;
        hp.x = pack_h_hi(v.x, v.y);
        hp.y = pack_h_hi(v.z, v.w);
        ((uint2*)d)[i] = hp;
        return;
    }

    __shared__ float s[64][65];
    const int b = z, k0 = blockIdx.y * 64, t0 = blockIdx.x * 64;
    const float* src = x + ((size_t)b * HID + k0) * TDIM + t0;
#pragma unroll
    for (int i = 0; i < 4; ++i) {
        const int u  = i * 256 + tid;
        const int r  = u >> 4;
        const int c4 = u & 15;
        const float4 v = *(const float4*)(src + (size_t)r * TDIM + c4 * 4);
        s[r][c4 * 4 + 0] = v.x;
        s[r][c4 * 4 + 1] = v.y;
        s[r][c4 * 4 + 2] = v.z;
        s[r][c4 * 4 + 3] = v.w;
    }
    __syncthreads();

    const int t  = tid >> 2;
    const int kc = (tid & 3) * 16;
    uint32_t o[8];
#pragma unroll
    for (int i = 0; i < 8; ++i)
        o[i] = pack_h_hi(s[kc + 2 * i][t], s[kc + 2 * i + 1][t]);
    __half* dst = xh + (size_t)(b * TDIM + t0 + t) * HID + k0 + kc;
    *(uint4*)(dst)     = make_uint4(o[0], o[1], o[2], o[3]);
    *(uint4*)(dst + 8) = make_uint4(o[4], o[5], o[6], o[7]);
}

// ---------------------------------------------------------------------------
extern "C" void kernel_launch(void* const* d_in, const int* in_sizes, int n_in,
                              void* d_out, int out_size)
{
    const float* x    = (const float*)d_in[0];
    const int*   mask = (const int*)d_in[1];
    const float* Wq   = (const float*)d_in[2];
    const float* bq   = (const float*)d_in[3];
    const float* Wk   = (const float*)d_in[4];
    const float* bk   = (const float*)d_in[5];
    const float* Wv   = (const float*)d_in[6];
    const float* bv   = (const float*)d_in[7];
    const float* Wo   = (const float*)d_in[8];
    const float* bo   = (const float*)d_in[9];
    float* out = (float*)d_out;

    float* scr;
    __half *xh, *qh, *kh, *vh, *ch, *whf;
    cudaGetSymbolAddress((void**)&scr, g_scr);
    cudaGetSymbolAddress((void**)&xh,  g_xh);
    cudaGetSymbolAddress((void**)&qh,  g_qh);
    cudaGetSymbolAddress((void**)&kh,  g_kh);
    cudaGetSymbolAddress((void**)&vh,  g_vh);
    cudaGetSymbolAddress((void**)&ch,  g_ch);
    cudaGetSymbolAddress((void**)&whf, g_whf);

    cudaFuncSetAttribute(gemm_qkv_kernel,
                         cudaFuncAttributeMaxDynamicSharedMemorySize, GEMM_SMEM_BYTES);
    cudaFuncSetAttribute(gemm_omax_kernel,
                         cudaFuncAttributeMaxDynamicSharedMemorySize, GEMM_SMEM_BYTES);
    cudaFuncSetAttribute(attn_mma_kernel,
                         cudaFuncAttributeMaxDynamicSharedMemorySize, ATTN_SMEM_BYTES);

    prep_kernel<<<dim3(8, 16, 64), 256>>>(x, xh, Wq, Wk, Wv, Wo, whf);

    const size_t WSZ = (size_t)HID * HID;

    gemm_qkv_kernel<<<dim3(HID / 128, BT / 128, 3), 256, GEMM_SMEM_BYTES>>>(
        xh, whf, bq, bk, bv, qh, kh, vh);

    attn_mma_kernel<<<dim3(TDIM / 128, NH, BDIM), 256, ATTN_SMEM_BYTES>>>(
        qh, kh, vh, mask, ch);

    gemm_omax_kernel<<<dim3(HID / 128, BT / 128), 256, GEMM_SMEM_BYTES>>>(
        ch, whf + 3 * WSZ, scr);

    maxcombine_kernel<<<(BDIM * HID) / 256, 256>>>(scr, bo, out);
}